// round 15
// baseline (speedup 1.0000x reference)
#include <cuda_runtime.h>

#define NB 8
#define NP 2048
#define KNN 20
#define CF 323
#define NEG 0.2f
#define FINF __int_as_float(0x7f800000)

typedef unsigned long long ull;

// ---------------- scratch (device globals; no allocations) ----------------
__device__ float g_feat[NB*NP*CF];      // [b][n][c] : pts|f1|f2|f3|f4
__device__ float g_featT[NB*CF*NP];     // [b][c][n]
__device__ float g_sq[NB*NP];
__device__ int   g_knn[NB*NP*KNN];
__device__ float g_A[NB*NP*128];        // feat @ Wd^T
__device__ float g_B2[NB*NP*128];       // feat @ Wc^T
__device__ float g_dot[NB*NP*NP];       // running pairwise dot products (134 MB)
__device__ float g_WT[75648];           // all-stage transposed W: [c][2*COUT]
__device__ float g_W5T[323*1024];
__device__ unsigned int g_gmax[NB*1024];
__device__ float g_h1[NB*512];
__device__ float g_h2[NB*256];

// g_WT per-stage float offsets (layout: [c][2*COUT])
#define WOFF1 0
#define WOFF2 384
#define WOFF3 8960
#define WOFF4 25728

__device__ __forceinline__ unsigned enc_f(float f){
    unsigned u = __float_as_uint(f);
    return (u & 0x80000000u) ? ~u : (u | 0x80000000u);
}
__device__ __forceinline__ float dec_f(unsigned u){
    return (u & 0x80000000u) ? __uint_as_float(u ^ 0x80000000u) : __uint_as_float(~u);
}
__device__ __forceinline__ float lrelu(float z){ return z > 0.f ? z : NEG*z; }

// packed f32x2 helpers (sm_103a FFMA2)
__device__ __forceinline__ ull pack2(float lo, float hi){
    ull r; asm("mov.b64 %0, {%1, %2};" : "=l"(r)
               : "r"(__float_as_uint(lo)), "r"(__float_as_uint(hi)));
    return r;
}
__device__ __forceinline__ void unpack2(ull v, float& lo, float& hi){
    unsigned a, b; asm("mov.b64 {%0, %1}, %2;" : "=r"(a), "=r"(b) : "l"(v));
    lo = __uint_as_float(a); hi = __uint_as_float(b);
}
__device__ __forceinline__ void fma2(ull& d, ull a, ull b){
    asm("fma.rn.f32x2 %0, %1, %2, %0;" : "+l"(d) : "l"(a), "l"(b));
}

// ---------------- init: transpose x, stage-1 norms, reset maxpool ---------
__global__ void k_init(const float* __restrict__ x){
    int idx = blockIdx.x*256 + threadIdx.x;       // NB*NP threads
    int b = idx >> 11, n = idx & (NP-1);
    float s = 0.f;
    #pragma unroll
    for (int c = 0; c < 3; c++){
        float v = x[(b*3 + c)*NP + n];
        g_feat[idx*CF + c] = v;
        g_featT[(b*CF + c)*NP + n] = v;
        s = fmaf(v, v, s);
    }
    g_sq[idx] = s;
    if (idx < NB*1024) g_gmax[idx] = 0u;
}

// ---------------- all weight prep: stage Ws transposed + W5 transposed ----
__global__ void k_wprep(const float* __restrict__ W1, const float* __restrict__ W2,
                        const float* __restrict__ W3, const float* __restrict__ W4,
                        const float* __restrict__ W5){
    int idx = blockIdx.x*256 + threadIdx.x;
    if (idx < 75648){
        const float* W; int CIN, COUT, off, base;
        if      (idx <   384){ W = W1; CIN =   3; COUT =  64; off = WOFF1; base =     0; }
        else if (idx <  8960){ W = W2; CIN =  67; COUT =  64; off = WOFF2; base =   384; }
        else if (idx < 25728){ W = W3; CIN = 131; COUT =  64; off = WOFF3; base =  8960; }
        else                 { W = W4; CIN = 195; COUT = 128; off = WOFF4; base = 25728; }
        int k = idx - base;
        int c = k % CIN; int rest = k / CIN;
        int o = rest % COUT; int half = rest / COUT;
        g_WT[off + c*2*COUT + half*COUT + o] = W[o*2*CIN + half*CIN + c];
    } else {
        int k = idx - 75648;
        if (k < 1024*323){
            int o = k / 323, c = k - o*323;
            g_W5T[c*1024 + o] = W5[k];
        }
    }
}

// ---------------- fused incremental-dot GEMM + top-20 selection -----------
// Block = 8 query rows x 2048 cols (64KB key -> 3 CTAs/SM).
// acc layout: [row-pair][col]; row pairs loaded as packed u64 from rfT,
// column value duplicated. key[i][j] = sq_j - 2*dot(i,j).
template<int C0, int C1, bool INIT, bool STORE>
__global__ __launch_bounds__(256, 3) void k_dist_topk(){
    extern __shared__ float sh[];
    float* key = sh;                 // 8*NP floats (64 KB)
    float* rfT = sh + 8*NP;          // (C1-C0)*8 floats, [c][row]
    const int b  = blockIdx.y;
    const int i0 = blockIdx.x * 8;
    const int tid = threadIdx.x;
    constexpr int CD = C1 - C0;

    for (int idx = tid; idx < 8*CD; idx += 256)
        rfT[idx] = g_feat[(b*NP + i0 + (idx & 7))*CF + C0 + (idx >> 3)];
    __syncthreads();

    const float* fT = g_featT + b*CF*NP + C0*NP;
    #pragma unroll 1
    for (int pass = 0; pass < 2; ++pass){
        const int j0 = pass*1024 + tid*4;
        ull acc[4][4];               // [pair p: rows 2p,2p+1][col q]
        if (INIT){
            #pragma unroll
            for (int p = 0; p < 4; p++)
                #pragma unroll
                for (int q = 0; q < 4; q++) acc[p][q] = 0ull;
        } else {
            #pragma unroll
            for (int p = 0; p < 4; p++){
                float4 d0 = __ldg((const float4*)(g_dot + (ull)(b*NP + i0 + 2*p    )*NP + j0));
                float4 d1 = __ldg((const float4*)(g_dot + (ull)(b*NP + i0 + 2*p + 1)*NP + j0));
                acc[p][0] = pack2(d0.x, d1.x); acc[p][1] = pack2(d0.y, d1.y);
                acc[p][2] = pack2(d0.z, d1.z); acc[p][3] = pack2(d0.w, d1.w);
            }
        }
        #pragma unroll 4
        for (int c = 0; c < CD; ++c){
            float4 v = __ldg((const float4*)(fT + c*NP + j0));
            ull vc0 = pack2(v.x, v.x), vc1 = pack2(v.y, v.y);
            ull vc2 = pack2(v.z, v.z), vc3 = pack2(v.w, v.w);
            const ull* rp = (const ull*)(rfT + c*8);
            #pragma unroll
            for (int p = 0; p < 4; ++p){
                ull r = rp[p];
                fma2(acc[p][0], r, vc0); fma2(acc[p][1], r, vc1);
                fma2(acc[p][2], r, vc2); fma2(acc[p][3], r, vc3);
            }
        }
        float4 sq4 = __ldg((const float4*)(g_sq + b*NP + j0));
        #pragma unroll
        for (int p = 0; p < 4; ++p){
            float4 dlo, dhi;
            unpack2(acc[p][0], dlo.x, dhi.x); unpack2(acc[p][1], dlo.y, dhi.y);
            unpack2(acc[p][2], dlo.z, dhi.z); unpack2(acc[p][3], dlo.w, dhi.w);
            if (STORE){
                *(float4*)(g_dot + (ull)(b*NP + i0 + 2*p    )*NP + j0) = dlo;
                *(float4*)(g_dot + (ull)(b*NP + i0 + 2*p + 1)*NP + j0) = dhi;
            }
            float4 o0, o1;
            o0.x = fmaf(-2.f, dlo.x, sq4.x); o0.y = fmaf(-2.f, dlo.y, sq4.y);
            o0.z = fmaf(-2.f, dlo.z, sq4.z); o0.w = fmaf(-2.f, dlo.w, sq4.w);
            o1.x = fmaf(-2.f, dhi.x, sq4.x); o1.y = fmaf(-2.f, dhi.y, sq4.y);
            o1.z = fmaf(-2.f, dhi.z, sq4.z); o1.w = fmaf(-2.f, dhi.w, sq4.w);
            *(float4*)(key + (2*p    )*NP + j0) = o0;
            *(float4*)(key + (2*p + 1)*NP + j0) = o1;
        }
    }
    __syncthreads();

    // ---- selection: warp w handles row w
    const int w = tid >> 5, L = tid & 31;
    float* krow = key + w*NP;
    float cm0 = FINF, cm1 = FINF;
    {
        const float4* c4 = (const float4*)(krow + L*32);
        const float4* d4 = (const float4*)(krow + (L + 32)*32);
        #pragma unroll
        for (int t = 0; t < 8; ++t){
            int tt = (t + L) & 7;
            float4 u = c4[tt];
            cm0 = fminf(cm0, fminf(fminf(u.x, u.y), fminf(u.z, u.w)));
            float4 v = d4[tt];
            cm1 = fminf(cm1, fminf(fminf(v.x, v.y), fminf(v.z, v.w)));
        }
    }
    int* knnp = g_knn + (b*NP + i0 + w)*KNN;
    for (int it = 0; it < KNN; ++it){
        float m = fminf(cm0, cm1);
        #pragma unroll
        for (int off = 16; off; off >>= 1)
            m = fminf(m, __shfl_xor_sync(0xffffffffu, m, off));
        unsigned e0 = __ballot_sync(0xffffffffu, cm0 == m);
        unsigned e1 = __ballot_sync(0xffffffffu, cm1 == m);
        int ch = e0 ? (__ffs(e0) - 1) : (32 + __ffs(e1) - 1);
        float v = krow[ch*32 + L];
        unsigned eq = __ballot_sync(0xffffffffu, v == m);
        int jl = __ffs(eq) - 1;
        int j = ch*32 + jl;
        if (L == jl){ krow[j] = FINF; v = FINF; }
        if (L == 0) knnp[it] = j;
        float nm = v;
        #pragma unroll
        for (int off = 16; off; off >>= 1)
            nm = fminf(nm, __shfl_xor_sync(0xffffffffu, nm, off));
        if (L == (ch & 31)){
            if (ch < 32) cm0 = nm; else cm1 = nm;
        }
    }
}

// ---------------- tiled projection GEMM: [32 pts] x [2*COUT] x CIN --------
// Weights chunk-staged through smem (latency-hiding), points pair-packed.
template<int CIN, int COUT>
__global__ __launch_bounds__(256) void k_proj2(int woff){
    constexpr int OD = 2*COUT;          // 128 or 256
    constexpr int NG = 256/OD;          // groups (2 or 1)
    constexpr int PT = 32/NG;           // points per thread (16 or 32)
    constexpr int CCH = 16;
    __shared__ __align__(16) float ptsT[CIN*32];
    __shared__ __align__(16) float wt[CCH*OD];
    int pbase = blockIdx.x * 32;
    int tid = threadIdx.x;
    int u = tid & (OD-1), g = tid / OD;

    for (int idx = tid; idx < 32*CIN; idx += 256){
        int p = idx / CIN, c = idx - p*CIN;
        ptsT[c*32 + p] = g_feat[(pbase + p)*CF + c];
    }

    ull acc[PT/2];
    #pragma unroll
    for (int t = 0; t < PT/2; t++) acc[t] = 0ull;

    for (int c0 = 0; c0 < CIN; c0 += CCH){
        __syncthreads();
        for (int idx = tid; idx < CCH*OD; idx += 256){
            int cc = idx / OD;
            if (c0 + cc < CIN) wt[idx] = g_WT[woff + (c0 + cc)*OD + (idx & (OD-1))];
        }
        __syncthreads();
        int cend = (CIN - c0 < CCH) ? (CIN - c0) : CCH;
        for (int cc = 0; cc < cend; ++cc){
            float w = wt[cc*OD + u];
            ull wp = pack2(w, w);
            const ull* pp = (const ull*)(ptsT + (c0 + cc)*32) + g*(PT/2);
            #pragma unroll
            for (int t = 0; t < PT/2; ++t) fma2(acc[t], wp, pp[t]);
        }
    }

    int o = (u < COUT) ? u : (u - COUT);
    float* dst = (u < COUT) ? g_A : g_B2;
    #pragma unroll
    for (int t = 0; t < PT/2; ++t){
        float v0, v1; unpack2(acc[t], v0, v1);
        int p = pbase + g*PT + 2*t;
        dst[(p    )*COUT + o] = v0;
        dst[(p + 1)*COUT + o] = v1;
    }
}

// ---------------- gather + affine + leaky + max over k (+ sq update) ------
// 4 points per block. DOSQ: deterministically add sum(y^2) to g_sq[P].
template<int COUT, bool DOSQ>
__global__ void k_edge_max(const float* __restrict__ sv, const float* __restrict__ bv,
                           int offout){
    __shared__ int idxs[4*KNN];
    __shared__ float red[16];
    int P0 = blockIdx.x*4;
    int t = threadIdx.x;
    if (t < 4*KNN) idxs[t] = g_knn[P0*KNN + t];
    __syncthreads();
    int p = t / COUT, o = t - p*COUT;
    int P = P0 + p;
    int b = P >> 11, n = P & (NP-1);
    float Ai = g_A[P*COUT + o];
    float Bi = g_B2[P*COUT + o];
    float base = Bi - Ai;
    float hmax = -3.4e38f, hmin = 3.4e38f;
    const int* ip = idxs + p*KNN;
    #pragma unroll
    for (int k = 0; k < KNN; k++){
        float v = g_A[(b*NP + ip[k])*COUT + o] + base;
        hmax = fmaxf(hmax, v); hmin = fminf(hmin, v);
    }
    float s = sv[o], bb = bv[o];
    float y = fmaxf(lrelu(fmaf(s, hmax, bb)), lrelu(fmaf(s, hmin, bb)));
    g_feat[P*CF + offout + o] = y;
    g_featT[(b*CF + offout + o)*NP + n] = y;
    if (DOSQ){
        float q = y*y;
        #pragma unroll
        for (int off = 16; off; off >>= 1)
            q += __shfl_xor_sync(0xffffffffu, q, off);
        if ((t & 31) == 0) red[t >> 5] = q;
        __syncthreads();
        constexpr int NW = COUT/32;
        if ((t & (COUT-1)) == 0){
            float sum = 0.f;
            #pragma unroll
            for (int k = 0; k < NW; k++) sum += red[(t >> 5) + k];
            g_sq[P] += sum;
        }
    }
}

// ---------------- global 1024-ch conv + max-pool over N -------------------
// Block: 32 points x 512 outs. Thread = 4 outs x 16 points.
// Per c: 1 LDG.128 (w float4) + 4 pack + 4 LDS.128 broadcast + 32 FFMA2.
__global__ __launch_bounds__(256) void k_glob(const float* __restrict__ s5,
                                              const float* __restrict__ b5){
    __shared__ __align__(16) float cfT[CF*32];    // [c][p], 41.3 KB
    int b = blockIdx.z;
    int p0 = blockIdx.x*32;
    for (int idx = threadIdx.x; idx < 32*CF; idx += 256){
        int p = idx / CF, c = idx - p*CF;
        cfT[c*32 + p] = g_feat[(b*NP + p0 + p)*CF + c];
    }
    __syncthreads();
    int og = threadIdx.x & 127;         // -> 4 consecutive outs
    int pg = threadIdx.x >> 7;          // -> 16 points (pg*16)
    int o = blockIdx.y*512 + og*4;
    ull acc[4][8];                      // [out][point-pair]
    #pragma unroll
    for (int k = 0; k < 4; k++)
        #pragma unroll
        for (int q = 0; q < 8; q++) acc[k][q] = 0ull;
    #pragma unroll 2
    for (int c = 0; c < CF; ++c){
        float4 wv = __ldg((const float4*)(g_W5T + c*1024 + o));
        ull w0 = pack2(wv.x, wv.x), w1 = pack2(wv.y, wv.y);
        ull w2 = pack2(wv.z, wv.z), w3 = pack2(wv.w, wv.w);
        const ulonglong2* pp = (const ulonglong2*)(cfT + c*32 + pg*16);
        ulonglong2 pA = pp[0], pB = pp[1], pC = pp[2], pD = pp[3];
        fma2(acc[0][0], w0, pA.x); fma2(acc[0][1], w0, pA.y);
        fma2(acc[0][2], w0, pB.x); fma2(acc[0][3], w0, pB.y);
        fma2(acc[0][4], w0, pC.x); fma2(acc[0][5], w0, pC.y);
        fma2(acc[0][6], w0, pD.x); fma2(acc[0][7], w0, pD.y);
        fma2(acc[1][0], w1, pA.x); fma2(acc[1][1], w1, pA.y);
        fma2(acc[1][2], w1, pB.x); fma2(acc[1][3], w1, pB.y);
        fma2(acc[1][4], w1, pC.x); fma2(acc[1][5], w1, pC.y);
        fma2(acc[1][6], w1, pD.x); fma2(acc[1][7], w1, pD.y);
        fma2(acc[2][0], w2, pA.x); fma2(acc[2][1], w2, pA.y);
        fma2(acc[2][2], w2, pB.x); fma2(acc[2][3], w2, pB.y);
        fma2(acc[2][4], w2, pC.x); fma2(acc[2][5], w2, pC.y);
        fma2(acc[2][6], w2, pD.x); fma2(acc[2][7], w2, pD.y);
        fma2(acc[3][0], w3, pA.x); fma2(acc[3][1], w3, pA.y);
        fma2(acc[3][2], w3, pB.x); fma2(acc[3][3], w3, pB.y);
        fma2(acc[3][4], w3, pC.x); fma2(acc[3][5], w3, pC.y);
        fma2(acc[3][6], w3, pD.x); fma2(acc[3][7], w3, pD.y);
    }
    #pragma unroll
    for (int k = 0; k < 4; ++k){
        float hmax = -3.4e38f, hmin = 3.4e38f;
        #pragma unroll
        for (int q = 0; q < 8; ++q){
            float x0, x1; unpack2(acc[k][q], x0, x1);
            hmax = fmaxf(hmax, fmaxf(x0, x1));
            hmin = fminf(hmin, fminf(x0, x1));
        }
        float s = s5[o + k], bb = b5[o + k];
        float y = fmaxf(lrelu(fmaf(s, hmax, bb)), lrelu(fmaf(s, hmin, bb)));
        atomicMax(&g_gmax[b*1024 + o + k], enc_f(y));
    }
}

// ---------------- emit gfeat part of output (off critical path) -----------
__global__ void k_finalize(float* __restrict__ out){
    int i = blockIdx.x*256 + threadIdx.x;        // NB*1024 threads
    out[NB*40 + i] = dec_f(g_gmax[i]);
}

// ---------------- FC head: warp per output; layer 1 decodes g_gmax --------
template<int INDIM, bool DEC>
__global__ void k_fcw(const float* __restrict__ W, const float* __restrict__ bias,
                      const float* __restrict__ sv, const float* __restrict__ Bv,
                      float* __restrict__ dout, int outdim, int layer){
    int b = blockIdx.x;
    int o = blockIdx.y*8 + (threadIdx.x >> 5);
    int L = threadIdx.x & 31;
    if (o >= outdim) return;
    const float* in = (layer == 2) ? (g_h1 + b*512) : (g_h2 + b*256);
    float* outp = (layer == 1) ? (g_h1 + b*512)
                : (layer == 2) ? (g_h2 + b*256) : (dout + b*40);
    const float4* Wr = (const float4*)(W + o*INDIM);
    const float4* vr = (const float4*)in;
    const uint4*  gr = (const uint4*)(g_gmax + b*1024);
    float a = 0.f;
    #pragma unroll
    for (int t = 0; t < INDIM/128; ++t){
        float4 w = __ldg(Wr + t*32 + L);
        float4 v;
        if (DEC){
            uint4 u = __ldg(gr + t*32 + L);
            v.x = dec_f(u.x); v.y = dec_f(u.y); v.z = dec_f(u.z); v.w = dec_f(u.w);
        } else {
            v = __ldg(vr + t*32 + L);
        }
        a = fmaf(w.x, v.x, fmaf(w.y, v.y, fmaf(w.z, v.z, fmaf(w.w, v.w, a))));
    }
    #pragma unroll
    for (int off = 16; off; off >>= 1)
        a += __shfl_xor_sync(0xffffffffu, a, off);
    if (L == 0){
        a += bias[o];
        if (layer != 3) a = lrelu(fmaf(a, sv[o], Bv[o]));
        outp[o] = a;
    }
}

// ---------------- launch --------------------------------------------------
extern "C" void kernel_launch(void* const* d_in, const int* in_sizes, int n_in,
                              void* d_out, int out_size){
    const float* x   = (const float*)d_in[0];
    const float* W1  = (const float*)d_in[1];
    const float* s1  = (const float*)d_in[2];
    const float* b1  = (const float*)d_in[3];
    const float* W2  = (const float*)d_in[4];
    const float* s2  = (const float*)d_in[5];
    const float* b2  = (const float*)d_in[6];
    const float* W3  = (const float*)d_in[7];
    const float* s3  = (const float*)d_in[8];
    const float* b3  = (const float*)d_in[9];
    const float* W4  = (const float*)d_in[10];
    const float* s4  = (const float*)d_in[11];
    const float* b4  = (const float*)d_in[12];
    const float* W5  = (const float*)d_in[13];
    const float* s5  = (const float*)d_in[14];
    const float* b5  = (const float*)d_in[15];
    const float* fW1 = (const float*)d_in[16];
    const float* fb1 = (const float*)d_in[17];
    const float* fs1 = (const float*)d_in[18];
    const float* fB1 = (const float*)d_in[19];
    const float* fW2 = (const float*)d_in[20];
    const float* fb2 = (const float*)d_in[21];
    const float* fs2 = (const float*)d_in[22];
    const float* fB2 = (const float*)d_in[23];
    const float* fW3 = (const float*)d_in[24];
    const float* fb3 = (const float*)d_in[25];
    float* out = (float*)d_out;

    const int sm1 = (8*NP + 8*3 ) * 4;
    const int sm2 = (8*NP + 8*67) * 4;
    const int smB = (8*NP + 8*64) * 4;
    cudaFuncSetAttribute((const void*)k_dist_topk<0,3,true,false>,
                         cudaFuncAttributeMaxDynamicSharedMemorySize, sm1);
    cudaFuncSetAttribute((const void*)k_dist_topk<0,67,true,true>,
                         cudaFuncAttributeMaxDynamicSharedMemorySize, sm2);
    cudaFuncSetAttribute((const void*)k_dist_topk<67,131,false,true>,
                         cudaFuncAttributeMaxDynamicSharedMemorySize, smB);
    cudaFuncSetAttribute((const void*)k_dist_topk<131,195,false,false>,
                         cudaFuncAttributeMaxDynamicSharedMemorySize, smB);

    k_init<<<NB*NP/256, 256>>>(x);
    k_wprep<<<(75648 + 1024*323 + 255)/256, 256>>>(W1, W2, W3, W4, W5);

    // ---- EdgeConv stage 1: Cin=3, Cout=64, out offset 3
    k_dist_topk<0,3,true,false><<<dim3(NP/8, NB), 256, sm1>>>();
    k_proj2<3,64><<<NB*NP/32, 256>>>(WOFF1);
    k_edge_max<64,true><<<NB*NP/4, 256>>>(s1, b1, 3);

    // ---- EdgeConv stage 2: Cin=67, Cout=64, out offset 67
    k_dist_topk<0,67,true,true><<<dim3(NP/8, NB), 256, sm2>>>();
    k_proj2<67,64><<<NB*NP/32, 256>>>(WOFF2);
    k_edge_max<64,true><<<NB*NP/4, 256>>>(s2, b2, 67);

    // ---- EdgeConv stage 3: Cin=131, Cout=64, out offset 131
    k_dist_topk<67,131,false,true><<<dim3(NP/8, NB), 256, smB>>>();
    k_proj2<131,64><<<NB*NP/32, 256>>>(WOFF3);
    k_edge_max<64,true><<<NB*NP/4, 256>>>(s3, b3, 131);

    // ---- EdgeConv stage 4: Cin=195, Cout=128, out offset 195
    k_dist_topk<131,195,false,false><<<dim3(NP/8, NB), 256, smB>>>();
    k_proj2<195,128><<<NB*NP/32, 256>>>(WOFF4);
    k_edge_max<128,false><<<NB*NP/4, 512>>>(s4, b4, 195);

    // ---- Global conv (1024) + maxpool over N
    k_glob<<<dim3(NP/32, 2, NB), 256>>>(s5, b5);

    // ---- FC head (warp per output; layer 1 decodes g_gmax directly)
    k_fcw<1024,true ><<<dim3(NB, 64), 256>>>(fW1, fb1, fs1, fB1, out, 512, 1);
    k_fcw< 512,false><<<dim3(NB, 32), 256>>>(fW2, fb2, fs2, fB2, out, 256, 2);
    k_fcw< 256,false><<<dim3(NB,  5), 256>>>(fW3, fb3, fs2, fB2, out,  40, 3);

    // ---- gfeat output (independent of FC chain)
    k_finalize<<<NB*1024/256, 256>>>(out);
}

// round 16
// speedup vs baseline: 1.0668x; 1.0668x over previous
#include <cuda_runtime.h>

#define NB 8
#define NP 2048
#define KNN 20
#define CF 323
#define NEG 0.2f
#define FINF __int_as_float(0x7f800000)

typedef unsigned long long ull;

// ---------------- scratch (device globals; no allocations) ----------------
__device__ float g_feat[NB*NP*CF];      // [b][n][c] : pts|f1|f2|f3|f4
__device__ float g_featT[NB*CF*NP];     // [b][c][n]
__device__ float g_sq[NB*NP];
__device__ int   g_knn[NB*NP*KNN];
__device__ float g_A[NB*NP*128];        // feat @ Wd^T
__device__ float g_B2[NB*NP*128];       // feat @ Wc^T
__device__ float g_dot[NB*NP*NP];       // running pairwise dot products (134 MB)
__device__ float g_WT[75648];           // all-stage transposed W: [c][2*COUT]
__device__ float g_W5T[323*1024];
__device__ unsigned int g_gmax[NB*1024];
__device__ float g_gfeat[NB*1024];
__device__ float g_h1[NB*512];
__device__ float g_h2[NB*256];

// g_WT per-stage float offsets (layout: [c][2*COUT])
#define WOFF1 0
#define WOFF2 384
#define WOFF3 8960
#define WOFF4 25728

__device__ __forceinline__ unsigned enc_f(float f){
    unsigned u = __float_as_uint(f);
    return (u & 0x80000000u) ? ~u : (u | 0x80000000u);
}
__device__ __forceinline__ float dec_f(unsigned u){
    return (u & 0x80000000u) ? __uint_as_float(u ^ 0x80000000u) : __uint_as_float(~u);
}
__device__ __forceinline__ float lrelu(float z){ return z > 0.f ? z : NEG*z; }

// packed f32x2 helpers (sm_103a FFMA2)
__device__ __forceinline__ ull pack2(float lo, float hi){
    ull r; asm("mov.b64 %0, {%1, %2};" : "=l"(r)
               : "r"(__float_as_uint(lo)), "r"(__float_as_uint(hi)));
    return r;
}
__device__ __forceinline__ void unpack2(ull v, float& lo, float& hi){
    unsigned a, b; asm("mov.b64 {%0, %1}, %2;" : "=r"(a), "=r"(b) : "l"(v));
    lo = __uint_as_float(a); hi = __uint_as_float(b);
}
__device__ __forceinline__ void fma2(ull& d, ull a, ull b){
    asm("fma.rn.f32x2 %0, %1, %2, %0;" : "+l"(d) : "l"(a), "l"(b));
}

// ---------------- init: transpose x, stage-1 norms, reset maxpool ---------
__global__ void k_init(const float* __restrict__ x){
    int idx = blockIdx.x*256 + threadIdx.x;       // NB*NP threads
    int b = idx >> 11, n = idx & (NP-1);
    float s = 0.f;
    #pragma unroll
    for (int c = 0; c < 3; c++){
        float v = x[(b*3 + c)*NP + n];
        g_feat[idx*CF + c] = v;
        g_featT[(b*CF + c)*NP + n] = v;
        s = fmaf(v, v, s);
    }
    g_sq[idx] = s;
    if (idx < NB*1024) g_gmax[idx] = 0u;
}

// ---------------- all weight prep: stage Ws transposed + W5 transposed ----
__global__ void k_wprep(const float* __restrict__ W1, const float* __restrict__ W2,
                        const float* __restrict__ W3, const float* __restrict__ W4,
                        const float* __restrict__ W5){
    int idx = blockIdx.x*256 + threadIdx.x;
    if (idx < 75648){
        const float* W; int CIN, COUT, off, base;
        if      (idx <   384){ W = W1; CIN =   3; COUT =  64; off = WOFF1; base =     0; }
        else if (idx <  8960){ W = W2; CIN =  67; COUT =  64; off = WOFF2; base =   384; }
        else if (idx < 25728){ W = W3; CIN = 131; COUT =  64; off = WOFF3; base =  8960; }
        else                 { W = W4; CIN = 195; COUT = 128; off = WOFF4; base = 25728; }
        int k = idx - base;
        int c = k % CIN; int rest = k / CIN;
        int o = rest % COUT; int half = rest / COUT;
        g_WT[off + c*2*COUT + half*COUT + o] = W[o*2*CIN + half*CIN + c];
    } else {
        int k = idx - 75648;
        if (k < 1024*323){
            int o = k / 323, c = k - o*323;
            g_W5T[c*1024 + o] = W5[k];
        }
    }
}

// ---------------- fused incremental-dot GEMM + top-20 selection -----------
// Block = 8 query rows x 2048 cols (64KB key -> 3 CTAs/SM).
// acc layout: [row-pair][col]; row pairs loaded as packed u64 from rfT,
// column value duplicated. key[i][j] = sq_j - 2*dot(i,j).
template<int C0, int C1, bool INIT, bool STORE>
__global__ __launch_bounds__(256, 3) void k_dist_topk(){
    extern __shared__ float sh[];
    float* key = sh;                 // 8*NP floats (64 KB)
    float* rfT = sh + 8*NP;          // (C1-C0)*8 floats, [c][row]
    const int b  = blockIdx.y;
    const int i0 = blockIdx.x * 8;
    const int tid = threadIdx.x;
    constexpr int CD = C1 - C0;

    for (int idx = tid; idx < 8*CD; idx += 256)
        rfT[idx] = g_feat[(b*NP + i0 + (idx & 7))*CF + C0 + (idx >> 3)];
    __syncthreads();

    const float* fT = g_featT + b*CF*NP + C0*NP;
    #pragma unroll 1
    for (int pass = 0; pass < 2; ++pass){
        const int j0 = pass*1024 + tid*4;
        ull acc[4][4];               // [pair p: rows 2p,2p+1][col q]
        if (INIT){
            #pragma unroll
            for (int p = 0; p < 4; p++)
                #pragma unroll
                for (int q = 0; q < 4; q++) acc[p][q] = 0ull;
        } else {
            #pragma unroll
            for (int p = 0; p < 4; p++){
                float4 d0 = __ldg((const float4*)(g_dot + (ull)(b*NP + i0 + 2*p    )*NP + j0));
                float4 d1 = __ldg((const float4*)(g_dot + (ull)(b*NP + i0 + 2*p + 1)*NP + j0));
                acc[p][0] = pack2(d0.x, d1.x); acc[p][1] = pack2(d0.y, d1.y);
                acc[p][2] = pack2(d0.z, d1.z); acc[p][3] = pack2(d0.w, d1.w);
            }
        }
        #pragma unroll 4
        for (int c = 0; c < CD; ++c){
            float4 v = __ldg((const float4*)(fT + c*NP + j0));
            ull vc0 = pack2(v.x, v.x), vc1 = pack2(v.y, v.y);
            ull vc2 = pack2(v.z, v.z), vc3 = pack2(v.w, v.w);
            const ull* rp = (const ull*)(rfT + c*8);
            #pragma unroll
            for (int p = 0; p < 4; ++p){
                ull r = rp[p];
                fma2(acc[p][0], r, vc0); fma2(acc[p][1], r, vc1);
                fma2(acc[p][2], r, vc2); fma2(acc[p][3], r, vc3);
            }
        }
        float4 sq4 = __ldg((const float4*)(g_sq + b*NP + j0));
        #pragma unroll
        for (int p = 0; p < 4; ++p){
            float4 dlo, dhi;
            unpack2(acc[p][0], dlo.x, dhi.x); unpack2(acc[p][1], dlo.y, dhi.y);
            unpack2(acc[p][2], dlo.z, dhi.z); unpack2(acc[p][3], dlo.w, dhi.w);
            if (STORE){
                *(float4*)(g_dot + (ull)(b*NP + i0 + 2*p    )*NP + j0) = dlo;
                *(float4*)(g_dot + (ull)(b*NP + i0 + 2*p + 1)*NP + j0) = dhi;
            }
            float4 o0, o1;
            o0.x = fmaf(-2.f, dlo.x, sq4.x); o0.y = fmaf(-2.f, dlo.y, sq4.y);
            o0.z = fmaf(-2.f, dlo.z, sq4.z); o0.w = fmaf(-2.f, dlo.w, sq4.w);
            o1.x = fmaf(-2.f, dhi.x, sq4.x); o1.y = fmaf(-2.f, dhi.y, sq4.y);
            o1.z = fmaf(-2.f, dhi.z, sq4.z); o1.w = fmaf(-2.f, dhi.w, sq4.w);
            *(float4*)(key + (2*p    )*NP + j0) = o0;
            *(float4*)(key + (2*p + 1)*NP + j0) = o1;
        }
    }
    __syncthreads();

    // ---- selection: warp w handles row w
    const int w = tid >> 5, L = tid & 31;
    float* krow = key + w*NP;
    float cm0 = FINF, cm1 = FINF;
    {
        const float4* c4 = (const float4*)(krow + L*32);
        const float4* d4 = (const float4*)(krow + (L + 32)*32);
        #pragma unroll
        for (int t = 0; t < 8; ++t){
            int tt = (t + L) & 7;
            float4 u = c4[tt];
            cm0 = fminf(cm0, fminf(fminf(u.x, u.y), fminf(u.z, u.w)));
            float4 v = d4[tt];
            cm1 = fminf(cm1, fminf(fminf(v.x, v.y), fminf(v.z, v.w)));
        }
    }
    int* knnp = g_knn + (b*NP + i0 + w)*KNN;
    for (int it = 0; it < KNN; ++it){
        float m = fminf(cm0, cm1);
        #pragma unroll
        for (int off = 16; off; off >>= 1)
            m = fminf(m, __shfl_xor_sync(0xffffffffu, m, off));
        unsigned e0 = __ballot_sync(0xffffffffu, cm0 == m);
        unsigned e1 = __ballot_sync(0xffffffffu, cm1 == m);
        int ch = e0 ? (__ffs(e0) - 1) : (32 + __ffs(e1) - 1);
        float v = krow[ch*32 + L];
        unsigned eq = __ballot_sync(0xffffffffu, v == m);
        int jl = __ffs(eq) - 1;
        int j = ch*32 + jl;
        if (L == jl){ krow[j] = FINF; v = FINF; }
        if (L == 0) knnp[it] = j;
        float nm = v;
        #pragma unroll
        for (int off = 16; off; off >>= 1)
            nm = fminf(nm, __shfl_xor_sync(0xffffffffu, nm, off));
        if (L == (ch & 31)){
            if (ch < 32) cm0 = nm; else cm1 = nm;
        }
    }
}

// ---------------- tiled projection GEMM: [32 pts] x [2*COUT] x CIN --------
// Weights chunk-staged through smem (latency-hiding), points pair-packed.
template<int CIN, int COUT>
__global__ __launch_bounds__(256) void k_proj2(int woff){
    constexpr int OD = 2*COUT;          // 128 or 256
    constexpr int NG = 256/OD;          // groups (2 or 1)
    constexpr int PT = 32/NG;           // points per thread (16 or 32)
    constexpr int CCH = 16;
    __shared__ __align__(16) float ptsT[CIN*32];
    __shared__ __align__(16) float wt[CCH*OD];
    int pbase = blockIdx.x * 32;
    int tid = threadIdx.x;
    int u = tid & (OD-1), g = tid / OD;

    for (int idx = tid; idx < 32*CIN; idx += 256){
        int p = idx / CIN, c = idx - p*CIN;
        ptsT[c*32 + p] = g_feat[(pbase + p)*CF + c];
    }

    ull acc[PT/2];
    #pragma unroll
    for (int t = 0; t < PT/2; t++) acc[t] = 0ull;

    for (int c0 = 0; c0 < CIN; c0 += CCH){
        __syncthreads();
        for (int idx = tid; idx < CCH*OD; idx += 256){
            int cc = idx / OD;
            if (c0 + cc < CIN) wt[idx] = g_WT[woff + (c0 + cc)*OD + (idx & (OD-1))];
        }
        __syncthreads();
        int cend = (CIN - c0 < CCH) ? (CIN - c0) : CCH;
        for (int cc = 0; cc < cend; ++cc){
            float w = wt[cc*OD + u];
            ull wp = pack2(w, w);
            const ull* pp = (const ull*)(ptsT + (c0 + cc)*32) + g*(PT/2);
            #pragma unroll
            for (int t = 0; t < PT/2; ++t) fma2(acc[t], wp, pp[t]);
        }
    }

    int o = (u < COUT) ? u : (u - COUT);
    float* dst = (u < COUT) ? g_A : g_B2;
    #pragma unroll
    for (int t = 0; t < PT/2; ++t){
        float v0, v1; unpack2(acc[t], v0, v1);
        int p = pbase + g*PT + 2*t;
        dst[(p    )*COUT + o] = v0;
        dst[(p + 1)*COUT + o] = v1;
    }
}

// ---------------- gather + affine + leaky + max over k (+ sq update) ------
// 4 points per block. DOSQ: deterministically add sum(y^2) to g_sq[P].
template<int COUT, bool DOSQ>
__global__ void k_edge_max(const float* __restrict__ sv, const float* __restrict__ bv,
                           int offout){
    __shared__ int idxs[4*KNN];
    __shared__ float red[16];
    int P0 = blockIdx.x*4;
    int t = threadIdx.x;
    if (t < 4*KNN) idxs[t] = g_knn[P0*KNN + t];
    __syncthreads();
    int p = t / COUT, o = t - p*COUT;
    int P = P0 + p;
    int b = P >> 11, n = P & (NP-1);
    float Ai = g_A[P*COUT + o];
    float Bi = g_B2[P*COUT + o];
    float base = Bi - Ai;
    float hmax = -3.4e38f, hmin = 3.4e38f;
    const int* ip = idxs + p*KNN;
    #pragma unroll
    for (int k = 0; k < KNN; k++){
        float v = g_A[(b*NP + ip[k])*COUT + o] + base;
        hmax = fmaxf(hmax, v); hmin = fminf(hmin, v);
    }
    float s = sv[o], bb = bv[o];
    float y = fmaxf(lrelu(fmaf(s, hmax, bb)), lrelu(fmaf(s, hmin, bb)));
    g_feat[P*CF + offout + o] = y;
    g_featT[(b*CF + offout + o)*NP + n] = y;
    if (DOSQ){
        float q = y*y;
        #pragma unroll
        for (int off = 16; off; off >>= 1)
            q += __shfl_xor_sync(0xffffffffu, q, off);
        if ((t & 31) == 0) red[t >> 5] = q;
        __syncthreads();
        constexpr int NW = COUT/32;
        if ((t & (COUT-1)) == 0){
            float sum = 0.f;
            #pragma unroll
            for (int k = 0; k < NW; k++) sum += red[(t >> 5) + k];
            g_sq[P] += sum;
        }
    }
}

// ---------------- global 1024-ch conv + max-pool over N -------------------
// 32 points x 512 outs per block; thread = 32 points x 2 outs, packed FFMA2.
__global__ __launch_bounds__(256) void k_glob(const float* __restrict__ s5,
                                              const float* __restrict__ b5){
    __shared__ __align__(16) float cfT[CF*32];    // [c][p], 41.3 KB
    int b = blockIdx.z;
    int p0 = blockIdx.x*32;
    for (int idx = threadIdx.x; idx < 32*CF; idx += 256){
        int p = idx / CF, c = idx - p*CF;
        cfT[c*32 + p] = g_feat[(b*NP + p0 + p)*CF + c];
    }
    __syncthreads();
    int o = blockIdx.y*512 + threadIdx.x*2;
    ull acc0[16], acc1[16];
    #pragma unroll
    for (int q = 0; q < 16; q++){ acc0[q] = 0ull; acc1[q] = 0ull; }
    const float* Wc = g_W5T + o;
    #pragma unroll 2
    for (int c = 0; c < CF; ++c){
        float2 wv = __ldg((const float2*)(Wc + c*1024));
        ull w0 = pack2(wv.x, wv.x), w1 = pack2(wv.y, wv.y);
        const float4* p4 = (const float4*)(cfT + c*32);
        #pragma unroll
        for (int q = 0; q < 8; ++q){
            float4 pv = p4[q];
            ull p01 = pack2(pv.x, pv.y), p23 = pack2(pv.z, pv.w);
            fma2(acc0[q*2  ], w0, p01); fma2(acc0[q*2+1], w0, p23);
            fma2(acc1[q*2  ], w1, p01); fma2(acc1[q*2+1], w1, p23);
        }
    }
    #pragma unroll
    for (int k = 0; k < 2; ++k){
        ull* a = k ? acc1 : acc0;
        float hmax = -3.4e38f, hmin = 3.4e38f;
        #pragma unroll
        for (int q = 0; q < 16; ++q){
            float x0, x1; unpack2(a[q], x0, x1);
            hmax = fmaxf(hmax, fmaxf(x0, x1));
            hmin = fminf(hmin, fminf(x0, x1));
        }
        float s = s5[o + k], bb = b5[o + k];
        float y = fmaxf(lrelu(fmaf(s, hmax, bb)), lrelu(fmaf(s, hmin, bb)));
        atomicMax(&g_gmax[b*1024 + o + k], enc_f(y));
    }
}

// ---------------- decode maxpool, emit gfeat ------------------------------
__global__ void k_finalize(float* __restrict__ out){
    int i = blockIdx.x*256 + threadIdx.x;        // NB*1024 threads
    float f = dec_f(g_gmax[i]);
    g_gfeat[i] = f;
    out[NB*40 + i] = f;                           // gfeat after logits
}

// ---------------- FC head: warp per output, coalesced float4 W reads ------
template<int INDIM>
__global__ void k_fcw(const float* __restrict__ W, const float* __restrict__ bias,
                      const float* __restrict__ sv, const float* __restrict__ Bv,
                      float* __restrict__ dout, int outdim, int layer){
    int b = blockIdx.x;
    int o = blockIdx.y*8 + (threadIdx.x >> 5);
    int L = threadIdx.x & 31;
    if (o >= outdim) return;
    const float* in = (layer == 1) ? (g_gfeat + b*1024)
                    : (layer == 2) ? (g_h1 + b*512) : (g_h2 + b*256);
    float* outp = (layer == 1) ? (g_h1 + b*512)
                : (layer == 2) ? (g_h2 + b*256) : (dout + b*40);
    const float4* Wr = (const float4*)(W + o*INDIM);
    const float4* vr = (const float4*)in;
    float a = 0.f;
    #pragma unroll
    for (int t = 0; t < INDIM/128; ++t){
        float4 w = __ldg(Wr + t*32 + L);
        float4 v = __ldg(vr + t*32 + L);
        a = fmaf(w.x, v.x, fmaf(w.y, v.y, fmaf(w.z, v.z, fmaf(w.w, v.w, a))));
    }
    #pragma unroll
    for (int off = 16; off; off >>= 1)
        a += __shfl_xor_sync(0xffffffffu, a, off);
    if (L == 0){
        a += bias[o];
        if (layer != 3) a = lrelu(fmaf(a, sv[o], Bv[o]));
        outp[o] = a;
    }
}

// ---------------- launch --------------------------------------------------
extern "C" void kernel_launch(void* const* d_in, const int* in_sizes, int n_in,
                              void* d_out, int out_size){
    const float* x   = (const float*)d_in[0];
    const float* W1  = (const float*)d_in[1];
    const float* s1  = (const float*)d_in[2];
    const float* b1  = (const float*)d_in[3];
    const float* W2  = (const float*)d_in[4];
    const float* s2  = (const float*)d_in[5];
    const float* b2  = (const float*)d_in[6];
    const float* W3  = (const float*)d_in[7];
    const float* s3  = (const float*)d_in[8];
    const float* b3  = (const float*)d_in[9];
    const float* W4  = (const float*)d_in[10];
    const float* s4  = (const float*)d_in[11];
    const float* b4  = (const float*)d_in[12];
    const float* W5  = (const float*)d_in[13];
    const float* s5  = (const float*)d_in[14];
    const float* b5  = (const float*)d_in[15];
    const float* fW1 = (const float*)d_in[16];
    const float* fb1 = (const float*)d_in[17];
    const float* fs1 = (const float*)d_in[18];
    const float* fB1 = (const float*)d_in[19];
    const float* fW2 = (const float*)d_in[20];
    const float* fb2 = (const float*)d_in[21];
    const float* fs2 = (const float*)d_in[22];
    const float* fB2 = (const float*)d_in[23];
    const float* fW3 = (const float*)d_in[24];
    const float* fb3 = (const float*)d_in[25];
    float* out = (float*)d_out;

    const int sm1 = (8*NP + 8*3 ) * 4;
    const int sm2 = (8*NP + 8*67) * 4;
    const int smB = (8*NP + 8*64) * 4;
    cudaFuncSetAttribute((const void*)k_dist_topk<0,3,true,false>,
                         cudaFuncAttributeMaxDynamicSharedMemorySize, sm1);
    cudaFuncSetAttribute((const void*)k_dist_topk<0,67,true,true>,
                         cudaFuncAttributeMaxDynamicSharedMemorySize, sm2);
    cudaFuncSetAttribute((const void*)k_dist_topk<67,131,false,true>,
                         cudaFuncAttributeMaxDynamicSharedMemorySize, smB);
    cudaFuncSetAttribute((const void*)k_dist_topk<131,195,false,false>,
                         cudaFuncAttributeMaxDynamicSharedMemorySize, smB);

    k_init<<<NB*NP/256, 256>>>(x);
    k_wprep<<<(75648 + 1024*323 + 255)/256, 256>>>(W1, W2, W3, W4, W5);

    // ---- EdgeConv stage 1: Cin=3, Cout=64, out offset 3
    k_dist_topk<0,3,true,false><<<dim3(NP/8, NB), 256, sm1>>>();
    k_proj2<3,64><<<NB*NP/32, 256>>>(WOFF1);
    k_edge_max<64,true><<<NB*NP/4, 256>>>(s1, b1, 3);

    // ---- EdgeConv stage 2: Cin=67, Cout=64, out offset 67
    k_dist_topk<0,67,true,true><<<dim3(NP/8, NB), 256, sm2>>>();
    k_proj2<67,64><<<NB*NP/32, 256>>>(WOFF2);
    k_edge_max<64,true><<<NB*NP/4, 256>>>(s2, b2, 67);

    // ---- EdgeConv stage 3: Cin=131, Cout=64, out offset 131
    k_dist_topk<67,131,false,true><<<dim3(NP/8, NB), 256, smB>>>();
    k_proj2<131,64><<<NB*NP/32, 256>>>(WOFF3);
    k_edge_max<64,true><<<NB*NP/4, 256>>>(s3, b3, 131);

    // ---- EdgeConv stage 4: Cin=195, Cout=128, out offset 195
    k_dist_topk<131,195,false,false><<<dim3(NP/8, NB), 256, smB>>>();
    k_proj2<195,128><<<NB*NP/32, 256>>>(WOFF4);
    k_edge_max<128,false><<<NB*NP/4, 512>>>(s4, b4, 195);

    // ---- Global conv (1024) + maxpool over N
    k_glob<<<dim3(NP/32, 2, NB), 256>>>(s5, b5);
    k_finalize<<<NB*1024/256, 256>>>(out);

    // ---- FC head (warp per output)
    k_fcw<1024><<<dim3(NB, 64), 256>>>(fW1, fb1, fs1, fB1, out, 512, 1);
    k_fcw< 512><<<dim3(NB, 32), 256>>>(fW2, fb2, fs2, fB2, out, 256, 2);
    k_fcw< 256><<<dim3(NB,  5), 256>>>(fW3, fb3, fs2, fB2, out,  40, 3);
}